// round 15
// baseline (speedup 1.0000x reference)
#include <cuda_runtime.h>
#include <math.h>

#define EPSF 1e-6f
#define NUM_V 10
#define IMG_H 1500
#define IMG_W 2000
#define IMG_HW (IMG_H * IMG_W)
#define MAXN 65536
#define MAXU (2 * 1024 * 1024)
#define SAMPLE_BLOCKS 1332
#define SAMPLE_THREADS 256

// ---------------- device scratch (no allocations allowed) ----------------
__device__ float4 g_ed[MAXN * 5];      // per-edge coefficients (19 floats in 5 float4)
__device__ int    g_map[MAXU];         // unit -> (edge << 10) | hx
__device__ uint2  g_img1[IMG_HW];      // u8 pair-pack: {r0,g0,b0,r1 | g1,b1,0,0}
__device__ uint2  g_img2[IMG_HW];
struct Accum {
    double acc[3];      // sim_sum, normal_sum, normalization_sum
    int    total;       // total units
    int    ticket;      // sample block completion counter
};
__device__ Accum g_A;

// ---------------- helpers ----------------
__device__ __forceinline__ void cross3(const float* u, const float* v, float* w) {
    w[0] = u[1] * v[2] - u[2] * v[1];
    w[1] = u[2] * v[0] - u[0] * v[2];
    w[2] = u[0] * v[1] - u[1] * v[0];
}
__device__ __forceinline__ float norm3(const float* u) {
    return sqrtf(u[0] * u[0] + u[1] * u[1] + u[2] * u[2]);
}
__device__ __forceinline__ unsigned int q8(float v) {
    return __float2uint_rn(__saturatef(v) * 255.0f);
}

// ---------------- convert: CHW fp32 -> u8 neighbor-pair, 8 px/thread, uint4 stores ----------------
__global__ void __launch_bounds__(256, 8)
convert_kernel(const float* __restrict__ rgb1,
               const float* __restrict__ rgb2) {
    if (blockIdx.x == 0 && threadIdx.x == 0) {
        g_A.acc[0] = 0.0; g_A.acc[1] = 0.0; g_A.acc[2] = 0.0;
        g_A.total = 0; g_A.ticket = 0;
    }
    const int npix8 = IMG_HW / 8;             // 375000, exact
    int t = blockIdx.x * blockDim.x + threadIdx.x;
    if (t >= 2 * npix8) return;
    int im = (t >= npix8) ? 1 : 0;
    int p8 = t - im * npix8;
    const float* src = im ? rgb2 : rgb1;
    uint2* dst = im ? g_img2 : g_img1;
    int i = p8 * 8;

    float4 ra = __ldg((const float4*)(src + i));
    float4 rb = __ldg((const float4*)(src + i + 4));
    float4 ga = __ldg((const float4*)(src + i + IMG_HW));
    float4 gb = __ldg((const float4*)(src + i + 4 + IMG_HW));
    float4 ba = __ldg((const float4*)(src + i + 2 * IMG_HW));
    float4 bb = __ldg((const float4*)(src + i + 4 + 2 * IMG_HW));
    int i9 = min(i + 8, IMG_HW - 1);
    float r9 = __ldg(src + i9);
    float g9 = __ldg(src + i9 + IMG_HW);
    float b9 = __ldg(src + i9 + 2 * IMG_HW);

    unsigned int R[9] = { q8(ra.x), q8(ra.y), q8(ra.z), q8(ra.w),
                          q8(rb.x), q8(rb.y), q8(rb.z), q8(rb.w), q8(r9) };
    unsigned int G[9] = { q8(ga.x), q8(ga.y), q8(ga.z), q8(ga.w),
                          q8(gb.x), q8(gb.y), q8(gb.z), q8(gb.w), q8(g9) };
    unsigned int B[9] = { q8(ba.x), q8(ba.y), q8(ba.z), q8(ba.w),
                          q8(bb.x), q8(bb.y), q8(bb.z), q8(bb.w), q8(b9) };

    uint4* dst4 = (uint4*)(dst + i);          // i % 8 == 0 -> 16B aligned
    #pragma unroll
    for (int q = 0; q < 4; q++) {
        int p = 2 * q;
        uint4 v;
        v.x = R[p]   | (G[p] << 8)   | (B[p] << 16)   | (R[p+1] << 24);
        v.y = G[p+1] | (B[p+1] << 8);
        v.z = R[p+1] | (G[p+1] << 8) | (B[p+1] << 16) | (R[p+2] << 24);
        v.w = G[p+2] | (B[p+2] << 8);
        dst4[q] = v;
    }
}

// ---------------- per-edge: T per-thread, coeffs, losses, coalesced map fill ----------------
__global__ void edge_kernel(const float* __restrict__ ep,
                            const float* __restrict__ K1,
                            const float* __restrict__ K2,
                            const float* __restrict__ E1,
                            const float* __restrict__ E2, int N) {
    int i = blockIdx.x * blockDim.x + threadIdx.x;
    float nloss = 0.0f, zloss = 0.0f;
    int my_b = 0, my_nh = 0;
    if (i < N && i < MAXN) {
        // T = K2h @ E2 @ inv(E1), per-thread (uniform data, no divergence)
        float a[4][8];
        for (int r = 0; r < 4; r++)
            for (int j = 0; j < 4; j++) {
                a[r][j] = E1[r * 4 + j];
                a[r][j + 4] = (r == j) ? 1.0f : 0.0f;
            }
        for (int col = 0; col < 4; col++) {
            int p = col; float best = fabsf(a[col][col]);
            for (int r = col + 1; r < 4; r++) {
                float v = fabsf(a[r][col]);
                if (v > best) { best = v; p = r; }
            }
            if (p != col)
                for (int j = 0; j < 8; j++) { float t = a[col][j]; a[col][j] = a[p][j]; a[p][j] = t; }
            float d = a[col][col];
            for (int j = 0; j < 8; j++) a[col][j] /= d;
            for (int r = 0; r < 4; r++) {
                if (r == col) continue;
                float f = a[r][col];
                for (int j = 0; j < 8; j++) a[r][j] -= f * a[col][j];
            }
        }
        float M[16];
        for (int r = 0; r < 4; r++)
            for (int j = 0; j < 4; j++) {
                float s = 0.0f;
                for (int kk = 0; kk < 4; kk++) s += E2[r * 4 + kk] * a[kk][j + 4];
                M[r * 4 + j] = s;
            }
        float T[12];
        for (int j = 0; j < 4; j++)
            for (int r = 0; r < 3; r++) {
                float s = 0.0f;
                for (int kk = 0; kk < 3; kk++) s += K2[r * 3 + kk] * M[kk * 4 + j];
                T[r * 4 + j] = s;
            }

        const float4* e4 = (const float4*)(ep + (size_t)i * 12);
        float4 q0 = e4[0], q1 = e4[1], q2 = e4[2];
        float p0[3] = { q0.x, q0.y, q0.z };
        float p1[3] = { q0.w, q1.x, q1.y };
        float p2[3] = { q1.z, q1.w, q2.x };
        float p3[3] = { q2.y, q2.z, q2.w };

        float cd[3] = { p1[0] - p0[0], p1[1] - p0[1], p1[2] - p0[2] };
        float nd[3] = { p3[0] - p1[0], p3[1] - p1[1], p3[2] - p1[2] };
        float pd[3] = { p0[0] - p2[0], p0[1] - p2[1], p0[2] - p2[2] };

        float ce[3] = { cd[0] + EPSF, cd[1] + EPSF, cd[2] + EPSF };
        float cl = norm3(ce);
        float dir[3] = { cd[0] / cl, cd[1] / cl, cd[2] / cl };

        float cn[3]; cross3(dir, nd, cn);
        float cnn = norm3(cn) + EPSF;
        cn[0] /= cnn; cn[1] /= cnn; cn[2] /= cnn;
        if (cn[2] > 0.0f) { cn[0] = -cn[0]; cn[1] = -cn[1]; cn[2] = -cn[2]; }

        float up[3]; cross3(cn, dir, up);
        float upn = norm3(up) + EPSF;
        up[0] /= upn; up[1] /= upn; up[2] /= upn;

        float pn[3]; cross3(pd, dir, pn);
        float pnn = norm3(pn) + EPSF;
        pn[0] /= pnn; pn[1] /= pnn; pn[2] /= pnn;

        int nh = (int)floorf(cl / 0.05f);
        nh = max(2, min(1000, nh));
        my_nh = nh;

        float k[9];
        #pragma unroll
        for (int t = 0; t < 9; t++) k[t] = K1[t];

        float A1[3], B1[3], C1[3], A2[3], B2[3], C2[3];
        #pragma unroll
        for (int r = 0; r < 3; r++) {
            A1[r] = k[r*3+0]*p0[0] + k[r*3+1]*p0[1] + k[r*3+2]*p0[2];
            B1[r] = k[r*3+0]*dir[0] + k[r*3+1]*dir[1] + k[r*3+2]*dir[2];
            C1[r] = k[r*3+0]*up[0] + k[r*3+1]*up[1] + k[r*3+2]*up[2];
            A2[r] = T[r*4+0]*p0[0] + T[r*4+1]*p0[1] + T[r*4+2]*p0[2] + T[r*4+3];
            B2[r] = T[r*4+0]*dir[0] + T[r*4+1]*dir[1] + T[r*4+2]*dir[2];
            C2[r] = T[r*4+0]*up[0] + T[r*4+1]*up[1] + T[r*4+2]*up[2];
        }
        float xstep = cl / (float)(nh - 1);

        g_ed[i*5+0] = make_float4(A1[0], A1[1], A1[2], B1[0]);
        g_ed[i*5+1] = make_float4(B1[1], B1[2], C1[0], C1[1]);
        g_ed[i*5+2] = make_float4(C1[2], A2[0], A2[1], A2[2]);
        g_ed[i*5+3] = make_float4(B2[0], B2[1], B2[2], C2[0]);
        g_ed[i*5+4] = make_float4(C2[1], C2[2], xstep, 0.0f);

        my_b = atomicAdd(&g_A.total, nh);

        nloss = 1.0f - (cn[0] * pn[0] + cn[1] * pn[1] + cn[2] * pn[2]);

        float obs[3]; cross3(p0, p1, obs);
        float obn = norm3(obs) + EPSF;
        obs[0] /= obn; obs[1] /= obn; obs[2] /= obn;
        float snp = fabsf(up[0] * obs[0] + up[1] * obs[1] + up[2] * obs[2]);
        snp = fminf(snp, 0.5f);
        zloss = 1.0f - snp * 2.0f;
    }

    // warp-cooperative coalesced map fill
    int lane = threadIdx.x & 31;
    int base_i = i - lane;
    #pragma unroll 1
    for (int l = 0; l < 32; l++) {
        int b_l  = __shfl_sync(0xffffffffu, my_b, l);
        int nh_l = __shfl_sync(0xffffffffu, my_nh, l);
        int tag  = (base_i + l) << 10;
        for (int u = lane; u < nh_l; u += 32) {
            int idx = b_l + u;
            if (idx < MAXU) g_map[idx] = tag | u;
        }
    }

    for (int o = 16; o > 0; o >>= 1) {
        nloss += __shfl_down_sync(0xffffffffu, nloss, o);
        zloss += __shfl_down_sync(0xffffffffu, zloss, o);
    }
    if ((threadIdx.x & 31) == 0) {
        atomicAdd(&g_A.acc[1], (double)nloss);
        atomicAdd(&g_A.acc[2], (double)zloss);
    }
}

// ---------------- bilinear fetch, u8 pair-packed (values scaled by 255) ----------------
__device__ __forceinline__ void fetch3q(const uint2* __restrict__ img,
                                        float u, float v, float out[3]) {
    float x = u * (float)(IMG_W - 1);
    float y = v * (float)(IMG_H - 1);
    int x0 = __float2int_rd(x);
    int y0 = __float2int_rd(y);
    float wx = x - (float)x0;
    float wy = y - (float)y0;
    float w00 = (1.0f - wx) * (1.0f - wy);
    float w10 = wx * (1.0f - wy);
    float w01 = (1.0f - wx) * wy;
    float w11 = wx * wy;
    const uint2* base = img + (size_t)(y0 * IMG_W + x0);
    uint2 ta = __ldg(base);          // row y0: px x0 and x0+1
    uint2 tb = __ldg(base + IMG_W);  // row y0+1
    float r00 = (float)(ta.x & 255u);
    float g00 = (float)((ta.x >> 8) & 255u);
    float b00 = (float)((ta.x >> 16) & 255u);
    float r10 = (float)(ta.x >> 24);
    float g10 = (float)(ta.y & 255u);
    float b10 = (float)((ta.y >> 8) & 255u);
    float r01 = (float)(tb.x & 255u);
    float g01 = (float)((tb.x >> 8) & 255u);
    float b01 = (float)((tb.x >> 16) & 255u);
    float r11 = (float)(tb.x >> 24);
    float g11 = (float)(tb.y & 255u);
    float b11 = (float)((tb.y >> 8) & 255u);
    out[0] = r00 * w00 + r10 * w10 + r01 * w01 + r11 * w11;
    out[1] = g00 * w00 + g10 * w10 + g01 * w01 + g11 * w11;
    out[2] = b00 * w00 + b10 * w10 + b01 * w01 + b11 * w11;
}

struct UnitCtx {
    float bu1, bv1, bw1, cu1, cv1, cw1;
    float bu2, bv2, bw2, cu2, cv2, cw2;
};

__device__ __forceinline__ UnitCtx load_ctx(int m) {
    const int e = m >> 10;
    const int hx = m & 1023;
    float4 d0 = g_ed[e*5+0];
    float4 d1 = g_ed[e*5+1];
    float4 d2 = g_ed[e*5+2];
    float4 d3 = g_ed[e*5+3];
    float4 d4 = g_ed[e*5+4];
    const float cx = (float)hx * d4.z;
    UnitCtx c;
    c.bu1 = fmaf(d0.w, cx, d0.x);
    c.bv1 = fmaf(d1.x, cx, d0.y);
    c.bw1 = fmaf(d1.y, cx, d0.z);
    c.cu1 = d1.z; c.cv1 = d1.w; c.cw1 = d2.x;
    c.bu2 = fmaf(d3.x, cx, d2.y);
    c.bv2 = fmaf(d3.y, cx, d2.z);
    c.bw2 = fmaf(d3.z, cx, d2.w);
    c.cu2 = d3.w; c.cv2 = d4.x; c.cw2 = d4.y;
    return c;
}

__device__ __forceinline__ void sample_j(const UnitCtx& c, float cy, float& local) {
    float u1n = fmaf(c.cu1, cy, c.bu1);
    float v1n = fmaf(c.cv1, cy, c.bv1);
    float w1n = fmaf(c.cw1, cy, c.bw1);
    float rw1 = __fdividef(1.0f, w1n);
    float u1 = fminf(fmaxf(u1n * rw1, 0.0f), 0.999999f);
    float v1 = fminf(fmaxf(v1n * rw1, 0.0f), 0.999999f);

    float u2n = fmaf(c.cu2, cy, c.bu2);
    float v2n = fmaf(c.cv2, cy, c.bv2);
    float w2n = fmaf(c.cw2, cy, c.bw2);
    float rw2 = __fdividef(1.0f, w2n);
    float u2 = fminf(fmaxf(u2n * rw2, 0.0f), 0.999999f);
    float v2 = fminf(fmaxf(v2n * rw2, 0.0f), 0.999999f);

    float s1[3], s2[3];
    fetch3q(g_img1, u1, v1, s1);
    fetch3q(g_img2, u2, v2, s2);
    float dd0 = s1[0] - s2[0];
    float dd1 = s1[1] - s2[1];
    float dd2 = s1[2] - s2[2];
    local = fmaf(dd0, dd0, local);
    local = fmaf(dd1, dd1, local);
    local = fmaf(dd2, dd2, local);
}

// ---------------- flat sample kernel, 2-way ILP, last block finalizes ----------------
__global__ void __launch_bounds__(SAMPLE_THREADS, 3)
sample_kernel(float* __restrict__ out, int N) {
    const int total = min(g_A.total, MAXU);
    const int stride = gridDim.x * blockDim.x;
    float locA = 0.0f, locB = 0.0f;

    for (int unit = blockIdx.x * blockDim.x + threadIdx.x; unit < total; unit += 2 * stride) {
        const int unitB = unit + stride;
        const bool hasB = (unitB < total);

        UnitCtx ca = load_ctx(__ldg(g_map + unit));
        UnitCtx cb = hasB ? load_ctx(__ldg(g_map + unitB)) : ca;

        #pragma unroll
        for (int j = 0; j < NUM_V; j++) {
            const float cy = (float)j * (0.5f / 9.0f);
            sample_j(ca, cy, locA);
            if (hasB) sample_j(cb, cy, locB);
        }
    }

    float local = locA + locB;
    for (int o = 16; o > 0; o >>= 1)
        local += __shfl_down_sync(0xffffffffu, local, o);
    __shared__ float warpsum[SAMPLE_THREADS / 32];
    int wid = threadIdx.x >> 5;
    if ((threadIdx.x & 31) == 0) warpsum[wid] = local;
    __syncthreads();
    if (threadIdx.x == 0) {
        float bs = 0.0f;
        #pragma unroll
        for (int w = 0; w < SAMPLE_THREADS / 32; w++) bs += warpsum[w];
        atomicAdd(&g_A.acc[0], (double)bs);
        __threadfence();
        int t = atomicAdd(&g_A.ticket, 1);
        if (t == (int)gridDim.x - 1) {     // last block finalizes
            double totalSamples = (double)g_A.total * (double)NUM_V * 3.0;
            out[0] = (float)(g_A.acc[0] / (65025.0 * totalSamples));  // 255^2 scale
            out[1] = (float)(g_A.acc[1] / (double)N / 2.0);
            out[2] = (float)(g_A.acc[2] / (double)N);
        }
    }
}

// ---------------- launch ----------------
extern "C" void kernel_launch(void* const* d_in, const int* in_sizes, int n_in,
                              void* d_out, int out_size) {
    const float* edge_points = (const float*)d_in[0];
    const float* intrinsic1  = (const float*)d_in[1];
    const float* intrinsic2  = (const float*)d_in[2];
    const float* extrinsic1  = (const float*)d_in[3];
    const float* extrinsic2  = (const float*)d_in[4];
    const float* rgb1        = (const float*)d_in[5];
    const float* rgb2        = (const float*)d_in[6];
    float* out = (float*)d_out;

    int N = in_sizes[0] / 12;
    int convThreads = 2 * (IMG_HW / 8);

    convert_kernel<<<(convThreads + 255) / 256, 256>>>(rgb1, rgb2);
    edge_kernel<<<(N + 255) / 256, 256>>>(edge_points, intrinsic1, intrinsic2,
                                          extrinsic1, extrinsic2, N);
    sample_kernel<<<SAMPLE_BLOCKS, SAMPLE_THREADS>>>(out, N);
}

// round 16
// speedup vs baseline: 1.5355x; 1.5355x over previous
#include <cuda_runtime.h>
#include <math.h>

#define EPSF 1e-6f
#define NUM_V 10
#define IMG_H 1500
#define IMG_W 2000
#define IMG_HW (IMG_H * IMG_W)
#define MAXN 65536
#define MAXU (2 * 1024 * 1024)
#define SAMPLE_BLOCKS 1332
#define SAMPLE_THREADS 256

// ---------------- device scratch (no allocations allowed) ----------------
__device__ float4 g_ed[MAXN * 5];      // per-edge coefficients (19 floats in 5 float4)
__device__ int    g_map[MAXU];         // unit -> (edge << 10) | hx
__device__ uint2  g_img1[IMG_HW];      // u8 pair-pack: {r0,g0,b0,r1 | g1,b1,0,0}
__device__ uint2  g_img2[IMG_HW];
struct Accum {
    double acc[3];      // sim_sum, normal_sum, normalization_sum
    int    total;       // total units
    int    ticket;      // sample block completion counter
};
__device__ Accum g_A;

// ---------------- helpers ----------------
__device__ __forceinline__ void cross3(const float* u, const float* v, float* w) {
    w[0] = u[1] * v[2] - u[2] * v[1];
    w[1] = u[2] * v[0] - u[0] * v[2];
    w[2] = u[0] * v[1] - u[1] * v[0];
}
__device__ __forceinline__ float norm3(const float* u) {
    return sqrtf(u[0] * u[0] + u[1] * u[1] + u[2] * u[2]);
}
__device__ __forceinline__ unsigned int q8(float v) {
    return __float2uint_rn(__saturatef(v) * 255.0f);
}

// ---------------- convert: CHW fp32 -> u8 neighbor-pair ----------------
// R12 mapping (4 px/thread, lane stride 16B, fully coalesced) but each thread
// handles the SAME pixel group in BOTH images -> 12 independent loads in flight.
__global__ void __launch_bounds__(256, 4)
convert_kernel(const float* __restrict__ rgb1,
               const float* __restrict__ rgb2) {
    if (blockIdx.x == 0 && threadIdx.x == 0) {
        g_A.acc[0] = 0.0; g_A.acc[1] = 0.0; g_A.acc[2] = 0.0;
        g_A.total = 0; g_A.ticket = 0;
    }
    const int npix4 = IMG_HW / 4;             // 1.5M, exact
    int t = blockIdx.x * blockDim.x + threadIdx.x;
    if (t >= npix4) return;
    int i = t * 4;
    int i5 = min(i + 4, IMG_HW - 1);

    // ---- issue all 12 loads up front (6 per image) ----
    float4 ar = __ldg((const float4*)(rgb1 + i));
    float4 ag = __ldg((const float4*)(rgb1 + i + IMG_HW));
    float4 ab = __ldg((const float4*)(rgb1 + i + 2 * IMG_HW));
    float4 br = __ldg((const float4*)(rgb2 + i));
    float4 bg = __ldg((const float4*)(rgb2 + i + IMG_HW));
    float4 bb = __ldg((const float4*)(rgb2 + i + 2 * IMG_HW));
    float ar5 = __ldg(rgb1 + i5);
    float ag5 = __ldg(rgb1 + i5 + IMG_HW);
    float ab5 = __ldg(rgb1 + i5 + 2 * IMG_HW);
    float br5 = __ldg(rgb2 + i5);
    float bg5 = __ldg(rgb2 + i5 + IMG_HW);
    float bb5 = __ldg(rgb2 + i5 + 2 * IMG_HW);

    {   // image 1 pack + 2x uint4 store
        unsigned int R[5] = { q8(ar.x), q8(ar.y), q8(ar.z), q8(ar.w), q8(ar5) };
        unsigned int G[5] = { q8(ag.x), q8(ag.y), q8(ag.z), q8(ag.w), q8(ag5) };
        unsigned int B[5] = { q8(ab.x), q8(ab.y), q8(ab.z), q8(ab.w), q8(ab5) };
        uint4* d4 = (uint4*)(g_img1 + i);      // i%4==0 -> 32B aligned
        uint4 v0, v1;
        v0.x = R[0] | (G[0] << 8) | (B[0] << 16) | (R[1] << 24);
        v0.y = G[1] | (B[1] << 8);
        v0.z = R[1] | (G[1] << 8) | (B[1] << 16) | (R[2] << 24);
        v0.w = G[2] | (B[2] << 8);
        v1.x = R[2] | (G[2] << 8) | (B[2] << 16) | (R[3] << 24);
        v1.y = G[3] | (B[3] << 8);
        v1.z = R[3] | (G[3] << 8) | (B[3] << 16) | (R[4] << 24);
        v1.w = G[4] | (B[4] << 8);
        d4[0] = v0; d4[1] = v1;
    }
    {   // image 2 pack + 2x uint4 store
        unsigned int R[5] = { q8(br.x), q8(br.y), q8(br.z), q8(br.w), q8(br5) };
        unsigned int G[5] = { q8(bg.x), q8(bg.y), q8(bg.z), q8(bg.w), q8(bg5) };
        unsigned int B[5] = { q8(bb.x), q8(bb.y), q8(bb.z), q8(bb.w), q8(bb5) };
        uint4* d4 = (uint4*)(g_img2 + i);
        uint4 v0, v1;
        v0.x = R[0] | (G[0] << 8) | (B[0] << 16) | (R[1] << 24);
        v0.y = G[1] | (B[1] << 8);
        v0.z = R[1] | (G[1] << 8) | (B[1] << 16) | (R[2] << 24);
        v0.w = G[2] | (B[2] << 8);
        v1.x = R[2] | (G[2] << 8) | (B[2] << 16) | (R[3] << 24);
        v1.y = G[3] | (B[3] << 8);
        v1.z = R[3] | (G[3] << 8) | (B[3] << 16) | (R[4] << 24);
        v1.w = G[4] | (B[4] << 8);
        d4[0] = v0; d4[1] = v1;
    }
}

// ---------------- per-edge: T per-thread, coeffs, losses, coalesced map fill ----------------
__global__ void edge_kernel(const float* __restrict__ ep,
                            const float* __restrict__ K1,
                            const float* __restrict__ K2,
                            const float* __restrict__ E1,
                            const float* __restrict__ E2, int N) {
    int i = blockIdx.x * blockDim.x + threadIdx.x;
    float nloss = 0.0f, zloss = 0.0f;
    int my_b = 0, my_nh = 0;
    if (i < N && i < MAXN) {
        // T = K2h @ E2 @ inv(E1), per-thread (uniform data, no divergence)
        float a[4][8];
        for (int r = 0; r < 4; r++)
            for (int j = 0; j < 4; j++) {
                a[r][j] = E1[r * 4 + j];
                a[r][j + 4] = (r == j) ? 1.0f : 0.0f;
            }
        for (int col = 0; col < 4; col++) {
            int p = col; float best = fabsf(a[col][col]);
            for (int r = col + 1; r < 4; r++) {
                float v = fabsf(a[r][col]);
                if (v > best) { best = v; p = r; }
            }
            if (p != col)
                for (int j = 0; j < 8; j++) { float t = a[col][j]; a[col][j] = a[p][j]; a[p][j] = t; }
            float d = a[col][col];
            for (int j = 0; j < 8; j++) a[col][j] /= d;
            for (int r = 0; r < 4; r++) {
                if (r == col) continue;
                float f = a[r][col];
                for (int j = 0; j < 8; j++) a[r][j] -= f * a[col][j];
            }
        }
        float M[16];
        for (int r = 0; r < 4; r++)
            for (int j = 0; j < 4; j++) {
                float s = 0.0f;
                for (int kk = 0; kk < 4; kk++) s += E2[r * 4 + kk] * a[kk][j + 4];
                M[r * 4 + j] = s;
            }
        float T[12];
        for (int j = 0; j < 4; j++)
            for (int r = 0; r < 3; r++) {
                float s = 0.0f;
                for (int kk = 0; kk < 3; kk++) s += K2[r * 3 + kk] * M[kk * 4 + j];
                T[r * 4 + j] = s;
            }

        const float4* e4 = (const float4*)(ep + (size_t)i * 12);
        float4 q0 = e4[0], q1 = e4[1], q2 = e4[2];
        float p0[3] = { q0.x, q0.y, q0.z };
        float p1[3] = { q0.w, q1.x, q1.y };
        float p2[3] = { q1.z, q1.w, q2.x };
        float p3[3] = { q2.y, q2.z, q2.w };

        float cd[3] = { p1[0] - p0[0], p1[1] - p0[1], p1[2] - p0[2] };
        float nd[3] = { p3[0] - p1[0], p3[1] - p1[1], p3[2] - p1[2] };
        float pd[3] = { p0[0] - p2[0], p0[1] - p2[1], p0[2] - p2[2] };

        float ce[3] = { cd[0] + EPSF, cd[1] + EPSF, cd[2] + EPSF };
        float cl = norm3(ce);
        float dir[3] = { cd[0] / cl, cd[1] / cl, cd[2] / cl };

        float cn[3]; cross3(dir, nd, cn);
        float cnn = norm3(cn) + EPSF;
        cn[0] /= cnn; cn[1] /= cnn; cn[2] /= cnn;
        if (cn[2] > 0.0f) { cn[0] = -cn[0]; cn[1] = -cn[1]; cn[2] = -cn[2]; }

        float up[3]; cross3(cn, dir, up);
        float upn = norm3(up) + EPSF;
        up[0] /= upn; up[1] /= upn; up[2] /= upn;

        float pn[3]; cross3(pd, dir, pn);
        float pnn = norm3(pn) + EPSF;
        pn[0] /= pnn; pn[1] /= pnn; pn[2] /= pnn;

        int nh = (int)floorf(cl / 0.05f);
        nh = max(2, min(1000, nh));
        my_nh = nh;

        float k[9];
        #pragma unroll
        for (int t = 0; t < 9; t++) k[t] = K1[t];

        float A1[3], B1[3], C1[3], A2[3], B2[3], C2[3];
        #pragma unroll
        for (int r = 0; r < 3; r++) {
            A1[r] = k[r*3+0]*p0[0] + k[r*3+1]*p0[1] + k[r*3+2]*p0[2];
            B1[r] = k[r*3+0]*dir[0] + k[r*3+1]*dir[1] + k[r*3+2]*dir[2];
            C1[r] = k[r*3+0]*up[0] + k[r*3+1]*up[1] + k[r*3+2]*up[2];
            A2[r] = T[r*4+0]*p0[0] + T[r*4+1]*p0[1] + T[r*4+2]*p0[2] + T[r*4+3];
            B2[r] = T[r*4+0]*dir[0] + T[r*4+1]*dir[1] + T[r*4+2]*dir[2];
            C2[r] = T[r*4+0]*up[0] + T[r*4+1]*up[1] + T[r*4+2]*up[2];
        }
        float xstep = cl / (float)(nh - 1);

        g_ed[i*5+0] = make_float4(A1[0], A1[1], A1[2], B1[0]);
        g_ed[i*5+1] = make_float4(B1[1], B1[2], C1[0], C1[1]);
        g_ed[i*5+2] = make_float4(C1[2], A2[0], A2[1], A2[2]);
        g_ed[i*5+3] = make_float4(B2[0], B2[1], B2[2], C2[0]);
        g_ed[i*5+4] = make_float4(C2[1], C2[2], xstep, 0.0f);

        my_b = atomicAdd(&g_A.total, nh);

        nloss = 1.0f - (cn[0] * pn[0] + cn[1] * pn[1] + cn[2] * pn[2]);

        float obs[3]; cross3(p0, p1, obs);
        float obn = norm3(obs) + EPSF;
        obs[0] /= obn; obs[1] /= obn; obs[2] /= obn;
        float snp = fabsf(up[0] * obs[0] + up[1] * obs[1] + up[2] * obs[2]);
        snp = fminf(snp, 0.5f);
        zloss = 1.0f - snp * 2.0f;
    }

    // warp-cooperative coalesced map fill
    int lane = threadIdx.x & 31;
    int base_i = i - lane;
    #pragma unroll 1
    for (int l = 0; l < 32; l++) {
        int b_l  = __shfl_sync(0xffffffffu, my_b, l);
        int nh_l = __shfl_sync(0xffffffffu, my_nh, l);
        int tag  = (base_i + l) << 10;
        for (int u = lane; u < nh_l; u += 32) {
            int idx = b_l + u;
            if (idx < MAXU) g_map[idx] = tag | u;
        }
    }

    for (int o = 16; o > 0; o >>= 1) {
        nloss += __shfl_down_sync(0xffffffffu, nloss, o);
        zloss += __shfl_down_sync(0xffffffffu, zloss, o);
    }
    if ((threadIdx.x & 31) == 0) {
        atomicAdd(&g_A.acc[1], (double)nloss);
        atomicAdd(&g_A.acc[2], (double)zloss);
    }
}

// ---------------- bilinear fetch, u8 pair-packed (values scaled by 255) ----------------
__device__ __forceinline__ void fetch3q(const uint2* __restrict__ img,
                                        float u, float v, float out[3]) {
    float x = u * (float)(IMG_W - 1);
    float y = v * (float)(IMG_H - 1);
    int x0 = __float2int_rd(x);
    int y0 = __float2int_rd(y);
    float wx = x - (float)x0;
    float wy = y - (float)y0;
    float w00 = (1.0f - wx) * (1.0f - wy);
    float w10 = wx * (1.0f - wy);
    float w01 = (1.0f - wx) * wy;
    float w11 = wx * wy;
    const uint2* base = img + (size_t)(y0 * IMG_W + x0);
    uint2 ta = __ldg(base);          // row y0: px x0 and x0+1
    uint2 tb = __ldg(base + IMG_W);  // row y0+1
    float r00 = (float)(ta.x & 255u);
    float g00 = (float)((ta.x >> 8) & 255u);
    float b00 = (float)((ta.x >> 16) & 255u);
    float r10 = (float)(ta.x >> 24);
    float g10 = (float)(ta.y & 255u);
    float b10 = (float)((ta.y >> 8) & 255u);
    float r01 = (float)(tb.x & 255u);
    float g01 = (float)((tb.x >> 8) & 255u);
    float b01 = (float)((tb.x >> 16) & 255u);
    float r11 = (float)(tb.x >> 24);
    float g11 = (float)(tb.y & 255u);
    float b11 = (float)((tb.y >> 8) & 255u);
    out[0] = r00 * w00 + r10 * w10 + r01 * w01 + r11 * w11;
    out[1] = g00 * w00 + g10 * w10 + g01 * w01 + g11 * w11;
    out[2] = b00 * w00 + b10 * w10 + b01 * w01 + b11 * w11;
}

struct UnitCtx {
    float bu1, bv1, bw1, cu1, cv1, cw1;
    float bu2, bv2, bw2, cu2, cv2, cw2;
};

__device__ __forceinline__ UnitCtx load_ctx(int m) {
    const int e = m >> 10;
    const int hx = m & 1023;
    float4 d0 = g_ed[e*5+0];
    float4 d1 = g_ed[e*5+1];
    float4 d2 = g_ed[e*5+2];
    float4 d3 = g_ed[e*5+3];
    float4 d4 = g_ed[e*5+4];
    const float cx = (float)hx * d4.z;
    UnitCtx c;
    c.bu1 = fmaf(d0.w, cx, d0.x);
    c.bv1 = fmaf(d1.x, cx, d0.y);
    c.bw1 = fmaf(d1.y, cx, d0.z);
    c.cu1 = d1.z; c.cv1 = d1.w; c.cw1 = d2.x;
    c.bu2 = fmaf(d3.x, cx, d2.y);
    c.bv2 = fmaf(d3.y, cx, d2.z);
    c.bw2 = fmaf(d3.z, cx, d2.w);
    c.cu2 = d3.w; c.cv2 = d4.x; c.cw2 = d4.y;
    return c;
}

__device__ __forceinline__ void sample_j(const UnitCtx& c, float cy, float& local) {
    float u1n = fmaf(c.cu1, cy, c.bu1);
    float v1n = fmaf(c.cv1, cy, c.bv1);
    float w1n = fmaf(c.cw1, cy, c.bw1);
    float rw1 = __fdividef(1.0f, w1n);
    float u1 = fminf(fmaxf(u1n * rw1, 0.0f), 0.999999f);
    float v1 = fminf(fmaxf(v1n * rw1, 0.0f), 0.999999f);

    float u2n = fmaf(c.cu2, cy, c.bu2);
    float v2n = fmaf(c.cv2, cy, c.bv2);
    float w2n = fmaf(c.cw2, cy, c.bw2);
    float rw2 = __fdividef(1.0f, w2n);
    float u2 = fminf(fmaxf(u2n * rw2, 0.0f), 0.999999f);
    float v2 = fminf(fmaxf(v2n * rw2, 0.0f), 0.999999f);

    float s1[3], s2[3];
    fetch3q(g_img1, u1, v1, s1);
    fetch3q(g_img2, u2, v2, s2);
    float dd0 = s1[0] - s2[0];
    float dd1 = s1[1] - s2[1];
    float dd2 = s1[2] - s2[2];
    local = fmaf(dd0, dd0, local);
    local = fmaf(dd1, dd1, local);
    local = fmaf(dd2, dd2, local);
}

// ---------------- flat sample kernel, 2-way ILP, last block finalizes ----------------
__global__ void __launch_bounds__(SAMPLE_THREADS, 3)
sample_kernel(float* __restrict__ out, int N) {
    const int total = min(g_A.total, MAXU);
    const int stride = gridDim.x * blockDim.x;
    float locA = 0.0f, locB = 0.0f;

    for (int unit = blockIdx.x * blockDim.x + threadIdx.x; unit < total; unit += 2 * stride) {
        const int unitB = unit + stride;
        const bool hasB = (unitB < total);

        UnitCtx ca = load_ctx(__ldg(g_map + unit));
        UnitCtx cb = hasB ? load_ctx(__ldg(g_map + unitB)) : ca;

        #pragma unroll
        for (int j = 0; j < NUM_V; j++) {
            const float cy = (float)j * (0.5f / 9.0f);
            sample_j(ca, cy, locA);
            if (hasB) sample_j(cb, cy, locB);
        }
    }

    float local = locA + locB;
    for (int o = 16; o > 0; o >>= 1)
        local += __shfl_down_sync(0xffffffffu, local, o);
    __shared__ float warpsum[SAMPLE_THREADS / 32];
    int wid = threadIdx.x >> 5;
    if ((threadIdx.x & 31) == 0) warpsum[wid] = local;
    __syncthreads();
    if (threadIdx.x == 0) {
        float bs = 0.0f;
        #pragma unroll
        for (int w = 0; w < SAMPLE_THREADS / 32; w++) bs += warpsum[w];
        atomicAdd(&g_A.acc[0], (double)bs);
        __threadfence();
        int t = atomicAdd(&g_A.ticket, 1);
        if (t == (int)gridDim.x - 1) {     // last block finalizes
            double totalSamples = (double)g_A.total * (double)NUM_V * 3.0;
            out[0] = (float)(g_A.acc[0] / (65025.0 * totalSamples));  // 255^2 scale
            out[1] = (float)(g_A.acc[1] / (double)N / 2.0);
            out[2] = (float)(g_A.acc[2] / (double)N);
        }
    }
}

// ---------------- launch ----------------
extern "C" void kernel_launch(void* const* d_in, const int* in_sizes, int n_in,
                              void* d_out, int out_size) {
    const float* edge_points = (const float*)d_in[0];
    const float* intrinsic1  = (const float*)d_in[1];
    const float* intrinsic2  = (const float*)d_in[2];
    const float* extrinsic1  = (const float*)d_in[3];
    const float* extrinsic2  = (const float*)d_in[4];
    const float* rgb1        = (const float*)d_in[5];
    const float* rgb2        = (const float*)d_in[6];
    float* out = (float*)d_out;

    int N = in_sizes[0] / 12;
    int convThreads = IMG_HW / 4;

    convert_kernel<<<(convThreads + 255) / 256, 256>>>(rgb1, rgb2);
    edge_kernel<<<(N + 255) / 256, 256>>>(edge_points, intrinsic1, intrinsic2,
                                          extrinsic1, extrinsic2, N);
    sample_kernel<<<SAMPLE_BLOCKS, SAMPLE_THREADS>>>(out, N);
}